// round 1
// baseline (speedup 1.0000x reference)
#include <cuda_runtime.h>

#define HID 1024
#define SEQ 1024
#define NB  4
#define NH  16
#define DH  64

// Scratch for q1,k1,v1,q2,k2,v2 : 6 x [B*S, HID] fp32 = ~100 MB
__device__ float g_qkv[6][NB * SEQ * HID];

struct QKVArgs {
    const float* x[2];
    const float* w[6];
    const float* b[6];
};

// ---------------------------------------------------------------------------
// QKV projection: C = X @ W + b   (M=4096, N=1024, K=1024)
// 128x128 block, BK=8, 256 threads, 8x8 register tile.
// ---------------------------------------------------------------------------
__global__ __launch_bounds__(256) void qkv_gemm(QKVArgs args) {
    __shared__ float As[8 * 132];   // transposed A tile, padded
    __shared__ float Bs[8 * 128];

    const int p = blockIdx.z;
    const float* X    = args.x[p / 3];
    const float* W    = args.w[p];
    const float* bias = args.b[p];
    float* C = g_qkv[p];

    const int tid = threadIdx.x;
    const int tx = tid & 15;    // col group (8 cols)
    const int ty = tid >> 4;    // row group (8 rows)
    const int bm = blockIdx.y << 7;
    const int bn = blockIdx.x << 7;

    const int ar = tid >> 1;          // 0..127
    const int ac = (tid & 1) << 2;    // 0 or 4
    const int br = tid >> 5;          // 0..7
    const int bc = (tid & 31) << 2;   // 0..124

    float acc[8][8];
#pragma unroll
    for (int i = 0; i < 8; i++)
#pragma unroll
        for (int j = 0; j < 8; j++) acc[i][j] = 0.f;

    for (int k0 = 0; k0 < HID; k0 += 8) {
        float4 av = *(const float4*)(X + (size_t)(bm + ar) * HID + k0 + ac);
        float4 bv = *(const float4*)(W + (size_t)(k0 + br) * HID + bn + bc);
        __syncthreads();
        As[(ac + 0) * 132 + ar] = av.x;
        As[(ac + 1) * 132 + ar] = av.y;
        As[(ac + 2) * 132 + ar] = av.z;
        As[(ac + 3) * 132 + ar] = av.w;
        *(float4*)(Bs + br * 128 + bc) = bv;
        __syncthreads();
#pragma unroll
        for (int k = 0; k < 8; k++) {
            float a[8], bb[8];
#pragma unroll
            for (int i = 0; i < 8; i++) a[i] = As[k * 132 + ty * 8 + i];
#pragma unroll
            for (int j = 0; j < 8; j++) bb[j] = Bs[k * 128 + tx * 8 + j];
#pragma unroll
            for (int i = 0; i < 8; i++)
#pragma unroll
                for (int j = 0; j < 8; j++)
                    acc[i][j] = fmaf(a[i], bb[j], acc[i][j]);
        }
    }

#pragma unroll
    for (int i = 0; i < 8; i++) {
#pragma unroll
        for (int j = 0; j < 8; j += 4) {
            float4 v;
            v.x = acc[i][j + 0] + bias[bn + tx * 8 + j + 0];
            v.y = acc[i][j + 1] + bias[bn + tx * 8 + j + 1];
            v.z = acc[i][j + 2] + bias[bn + tx * 8 + j + 2];
            v.w = acc[i][j + 3] + bias[bn + tx * 8 + j + 3];
            *(float4*)(C + (size_t)(bm + ty * 8 + i) * HID + bn + tx * 8 + j) = v;
        }
    }
}

// ---------------------------------------------------------------------------
// Fused cross-attention.
// One CTA = (stream, b, h, 32-row q block). Full score rows (32x1024) live in
// smem -> exact softmax, probs written once, then ctx = P @ V from smem.
// ---------------------------------------------------------------------------
#define SMEM_FLOATS (32 * 1024 + 64 * 32 + 64 * 257)
#define SMEM_BYTES  (SMEM_FLOATS * 4)

__global__ __launch_bounds__(256) void attn_kernel(const float* __restrict__ mask1,
                                                   const float* __restrict__ mask2,
                                                   float* __restrict__ out) {
    extern __shared__ float sm[];
    float* Ssc = sm;                    // [32][1024]
    float* Qs  = sm + 32 * 1024;        // [64][32]   (d-major, broadcast reads)
    float* Ks  = Qs + 64 * 32;          // [64][257]  (d-major, padded)
    float* Vs  = Ks;                    // reused: [128][65]

    const int qb = blockIdx.x;          // 0..31
    const int h  = blockIdx.y;          // 0..15
    const int b  = blockIdx.z >> 1;     // 0..3
    const int st = blockIdx.z & 1;      // 0: q1 x (k2,v2,mask2); 1: q2 x (k1,v1,mask1)

    const float* Q    = g_qkv[st * 3];
    const float* K    = st ? g_qkv[1] : g_qkv[4];
    const float* V    = st ? g_qkv[2] : g_qkv[5];
    const float* mask = st ? mask1 : mask2;

    float* probs = out + 8388608 + (size_t)st * 67108864
                 + ((size_t)(b * NH + h) * SEQ + qb * 32) * SEQ;
    float* ctx = out + (size_t)st * 4194304;

    const int tid = threadIdx.x;
    const int cg = tid & 31;            // strided cols: cg + 32*j
    const int rg = tid >> 5;            // 4 rows per group (rg constant per warp)

    // Load Q tile transposed: Qs[d][r]
    for (int i = tid; i < 32 * 64; i += 256) {
        int r = i >> 6, d = i & 63;
        Qs[d * 32 + r] = Q[(size_t)(b * SEQ + qb * 32 + r) * HID + h * DH + d];
    }

    // ---- scores: S = Q K^T / 8 + mask ----
    for (int kt = 0; kt < 4; kt++) {
        __syncthreads();
        for (int i = tid; i < 256 * 64; i += 256) {
            int c = i >> 6, d = i & 63;
            Ks[d * 257 + c] = K[(size_t)(b * SEQ + kt * 256 + c) * HID + h * DH + d];
        }
        __syncthreads();
        float acc[4][8];
#pragma unroll
        for (int i = 0; i < 4; i++)
#pragma unroll
            for (int j = 0; j < 8; j++) acc[i][j] = 0.f;

        for (int d = 0; d < 64; d++) {
            float q[4], kk[8];
#pragma unroll
            for (int i = 0; i < 4; i++) q[i] = Qs[d * 32 + rg * 4 + i];
#pragma unroll
            for (int j = 0; j < 8; j++) kk[j] = Ks[d * 257 + cg + 32 * j];
#pragma unroll
            for (int i = 0; i < 4; i++)
#pragma unroll
                for (int j = 0; j < 8; j++)
                    acc[i][j] = fmaf(q[i], kk[j], acc[i][j]);
        }
#pragma unroll
        for (int j = 0; j < 8; j++) {
            int col = kt * 256 + cg + 32 * j;
            float mk = mask[b * SEQ + col];
#pragma unroll
            for (int i = 0; i < 4; i++)
                Ssc[(rg * 4 + i) * 1024 + col] = acc[i][j] * 0.125f + mk;
        }
    }
    __syncthreads();

    // ---- softmax (exact, one warp per row group) ----
    {
        const int lane = tid & 31, warp = tid >> 5;
        for (int r = warp; r < 32; r += 8) {
            float* row = Ssc + r * 1024;
            float m = -1e30f;
            for (int c = lane; c < 1024; c += 32) m = fmaxf(m, row[c]);
#pragma unroll
            for (int o = 16; o >= 1; o >>= 1) m = fmaxf(m, __shfl_xor_sync(0xffffffffu, m, o));
            float s = 0.f;
            for (int c = lane; c < 1024; c += 32) {
                float e = __expf(row[c] - m);
                row[c] = e;
                s += e;
            }
#pragma unroll
            for (int o = 16; o >= 1; o >>= 1) s += __shfl_xor_sync(0xffffffffu, s, o);
            float inv = 1.f / s;
            for (int c = lane; c < 1024; c += 32) row[c] *= inv;
        }
    }
    __syncthreads();

    // ---- write probs (rows are contiguous in the output) ----
    for (int i = tid; i < 32 * 1024; i += 256) probs[i] = Ssc[i];

    // ---- ctx = P @ V ----
    float cacc[4][2] = {{0.f, 0.f}, {0.f, 0.f}, {0.f, 0.f}, {0.f, 0.f}};
    for (int kc = 0; kc < 8; kc++) {
        __syncthreads();
        for (int i = tid; i < 128 * 64; i += 256) {
            int kk = i >> 6, d = i & 63;
            Vs[kk * 65 + d] = V[(size_t)(b * SEQ + kc * 128 + kk) * HID + h * DH + d];
        }
        __syncthreads();
        for (int k2 = 0; k2 < 128; k2++) {
            float v0 = Vs[k2 * 65 + cg];
            float v1 = Vs[k2 * 65 + cg + 32];
#pragma unroll
            for (int i = 0; i < 4; i++) {
                float pv = Ssc[(rg * 4 + i) * 1024 + kc * 128 + k2];
                cacc[i][0] = fmaf(pv, v0, cacc[i][0]);
                cacc[i][1] = fmaf(pv, v1, cacc[i][1]);
            }
        }
    }
#pragma unroll
    for (int i = 0; i < 4; i++) {
        size_t base = (size_t)(b * SEQ + qb * 32 + rg * 4 + i) * HID + h * DH;
        ctx[base + cg]      = cacc[i][0];
        ctx[base + cg + 32] = cacc[i][1];
    }
}

// ---------------------------------------------------------------------------
extern "C" void kernel_launch(void* const* d_in, const int* in_sizes, int n_in,
                              void* d_out, int out_size) {
    (void)in_sizes; (void)n_in; (void)out_size;

    const float* m1 = (const float*)d_in[1];
    const float* m2 = (const float*)d_in[3];

    QKVArgs a;
    a.x[0] = (const float*)d_in[0];
    a.x[1] = (const float*)d_in[2];
    for (int i = 0; i < 6; i++) {
        a.w[i] = (const float*)d_in[4 + 2 * i];
        a.b[i] = (const float*)d_in[5 + 2 * i];
    }

    cudaFuncSetAttribute(attn_kernel, cudaFuncAttributeMaxDynamicSharedMemorySize,
                         SMEM_BYTES);

    qkv_gemm<<<dim3(8, 32, 6), 256>>>(a);
    attn_kernel<<<dim3(32, 16, 8), 256, SMEM_BYTES>>>(m1, m2, (float*)d_out);
}

// round 2
// speedup vs baseline: 1.3743x; 1.3743x over previous
#include <cuda_runtime.h>
#include <cstdint>

#define HID 1024
#define SEQ 1024
#define NB  4
#define NH  16
#define DH  64

// Scratch for q1,k1,v1,q2,k2,v2 : 6 x [B*S, HID] fp32 = ~100 MB
__device__ float g_qkv[6][NB * SEQ * HID];

struct QKVArgs {
    const float* x[2];
    const float* w[6];
    const float* b[6];
};

__device__ __forceinline__ uint32_t f2tf(float x) {
    uint32_t t;
    asm("cvt.rna.tf32.f32 %0, %1;" : "=r"(t) : "f"(x));
    return t;
}

__device__ __forceinline__ void mma_tf32(float* c, const uint32_t* a, const uint32_t* b) {
    asm volatile(
        "mma.sync.aligned.m16n8k8.row.col.f32.tf32.tf32.f32 "
        "{%0,%1,%2,%3}, {%4,%5,%6,%7}, {%8,%9}, {%0,%1,%2,%3};\n"
        : "+f"(c[0]), "+f"(c[1]), "+f"(c[2]), "+f"(c[3])
        : "r"(a[0]), "r"(a[1]), "r"(a[2]), "r"(a[3]), "r"(b[0]), "r"(b[1]));
}

// exp(x) via 2^t with degree-5 poly; ~2e-6 abs err, no MUFU.
__device__ __forceinline__ float fast_exp(float x) {
    x = fmaxf(x, -80.f);
    float t = x * 1.44269504f;
    float r = rintf(t);
    float f = t - r;
    float y = f * 0.69314718f;
    float p = 8.3333333e-3f;
    p = fmaf(p, y, 4.1666667e-2f);
    p = fmaf(p, y, 1.6666667e-1f);
    p = fmaf(p, y, 5.0e-1f);
    p = fmaf(p, y, 1.0f);
    p = fmaf(p, y, 1.0f);
    return __int_as_float(__float_as_int(p) + (((int)r) << 23));
}

// ---------------------------------------------------------------------------
// QKV projection: C = X @ W + b (M=4096, N=1024, K=1024), TF32 mma.
// 128x128 CTA tile, BK=32, 256 threads (8 warps, 2x4), warp tile 64x32.
// ---------------------------------------------------------------------------
__global__ __launch_bounds__(256, 2) void qkv_gemm(QKVArgs args) {
    __shared__ uint32_t As[128 * 36];   // [m][k], pitch 36 -> bank-free a-frags
    __shared__ uint32_t Bs[32 * 132];   // [k][n], pitch 132 -> bank-free b-frags

    const int p = blockIdx.z;
    const float* X    = args.x[p / 3];
    const float* W    = args.w[p];
    const float* bias = args.b[p];
    float* C = g_qkv[p];

    const int tid = threadIdx.x;
    const int wid = tid >> 5;
    const int lane = tid & 31;
    const int ly = lane >> 2;           // 0..7
    const int lx = lane & 3;            // 0..3
    const int warp_m = (wid & 1) * 64;
    const int warp_n = (wid >> 1) * 32;
    const int bm = blockIdx.y << 7;
    const int bn = blockIdx.x << 7;

    float acc[4][4][4];
#pragma unroll
    for (int i = 0; i < 4; i++)
#pragma unroll
        for (int j = 0; j < 4; j++)
#pragma unroll
            for (int q = 0; q < 4; q++) acc[i][j][q] = 0.f;

    for (int k0 = 0; k0 < HID; k0 += 32) {
        float4 av[4], bv[4];
#pragma unroll
        for (int i = 0; i < 4; i++) {
            int f = tid + i * 256;
            av[i] = *(const float4*)(X + (size_t)(bm + (f >> 3)) * HID + k0 + ((f & 7) << 2));
            bv[i] = *(const float4*)(W + (size_t)(k0 + (f >> 5)) * HID + bn + ((f & 31) << 2));
        }
        __syncthreads();
#pragma unroll
        for (int i = 0; i < 4; i++) {
            int f = tid + i * 256;
            uint32_t* pa = As + (f >> 3) * 36 + ((f & 7) << 2);
            pa[0] = f2tf(av[i].x); pa[1] = f2tf(av[i].y);
            pa[2] = f2tf(av[i].z); pa[3] = f2tf(av[i].w);
            uint32_t* pb = Bs + (f >> 5) * 132 + ((f & 31) << 2);
            pb[0] = f2tf(bv[i].x); pb[1] = f2tf(bv[i].y);
            pb[2] = f2tf(bv[i].z); pb[3] = f2tf(bv[i].w);
        }
        __syncthreads();
#pragma unroll
        for (int ks = 0; ks < 4; ks++) {
            const int kk = ks * 8;
            uint32_t a[4][4], b[4][2];
#pragma unroll
            for (int mi = 0; mi < 4; mi++) {
                int m = warp_m + mi * 16;
                a[mi][0] = As[(m + ly) * 36 + kk + lx];
                a[mi][1] = As[(m + ly + 8) * 36 + kk + lx];
                a[mi][2] = As[(m + ly) * 36 + kk + lx + 4];
                a[mi][3] = As[(m + ly + 8) * 36 + kk + lx + 4];
            }
#pragma unroll
            for (int ni = 0; ni < 4; ni++) {
                int n = warp_n + ni * 8;
                b[ni][0] = Bs[(kk + lx) * 132 + n + ly];
                b[ni][1] = Bs[(kk + lx + 4) * 132 + n + ly];
            }
#pragma unroll
            for (int mi = 0; mi < 4; mi++)
#pragma unroll
                for (int ni = 0; ni < 4; ni++)
                    mma_tf32(acc[mi][ni], a[mi], b[ni]);
        }
        __syncthreads();
    }

#pragma unroll
    for (int mi = 0; mi < 4; mi++) {
#pragma unroll
        for (int ni = 0; ni < 4; ni++) {
            int m = bm + warp_m + mi * 16 + ly;
            int n = bn + warp_n + ni * 8 + 2 * lx;
            float b0 = bias[n], b1 = bias[n + 1];
            float2 v0 = {acc[mi][ni][0] + b0, acc[mi][ni][1] + b1};
            float2 v1 = {acc[mi][ni][2] + b0, acc[mi][ni][3] + b1};
            *(float2*)(C + (size_t)m * HID + n) = v0;
            *(float2*)(C + (size_t)(m + 8) * HID + n) = v1;
        }
    }
}

// ---------------------------------------------------------------------------
// Fused cross-attention, TF32 mma. One CTA = (stream, b, h, 32 q-rows).
// Scores (32x1024 fp32) held in smem -> exact softmax (fast-exp), probs
// written once, then ctx = P@V with mma (P converted to tf32 at frag load).
// ---------------------------------------------------------------------------
#define SSC_PITCH 1028
#define KV_PITCH  72
#define Q_PITCH   68
#define ATTN_SMEM ((32 * SSC_PITCH + 32 * Q_PITCH + 128 * KV_PITCH) * 4)

__global__ __launch_bounds__(256) void attn_kernel(const float* __restrict__ mask1,
                                                   const float* __restrict__ mask2,
                                                   float* __restrict__ out) {
    extern __shared__ float sm[];
    float*    Ssc = sm;                                   // [32][1028]
    uint32_t* Qs  = (uint32_t*)(sm + 32 * SSC_PITCH);     // [32][68] tf32
    uint32_t* KVs = Qs + 32 * Q_PITCH;                    // [128][72] tf32

    const int qb = blockIdx.x;
    const int h  = blockIdx.y;
    const int b  = blockIdx.z >> 1;
    const int st = blockIdx.z & 1;

    const float* Q    = g_qkv[st * 3];
    const float* K    = st ? g_qkv[1] : g_qkv[4];
    const float* V    = st ? g_qkv[2] : g_qkv[5];
    const float* mask = st ? mask1 : mask2;

    float* probs = out + 8388608 + (size_t)st * 67108864
                 + ((size_t)(b * NH + h) * SEQ + qb * 32) * SEQ;
    float* ctx = out + (size_t)st * 4194304;

    const int tid = threadIdx.x;
    const int wid = tid >> 5;
    const int lane = tid & 31;
    const int ly = lane >> 2;
    const int lx = lane & 3;

    // Stage Q tile (tf32): Qs[r][d]
    for (int i = tid; i < 32 * 64; i += 256) {
        int r = i >> 6, d = i & 63;
        Qs[r * Q_PITCH + d] = f2tf(Q[(size_t)(b * SEQ + qb * 32 + r) * HID + h * DH + d]);
    }

    // ---- Phase 1: scores = QK^T/8 + mask, per 128-col K tile ----
    for (int kt = 0; kt < 8; kt++) {
        for (int i = tid; i < 128 * 64; i += 256) {
            int r = i >> 6, d = i & 63;
            KVs[r * KV_PITCH + d] =
                f2tf(K[(size_t)(b * SEQ + kt * 128 + r) * HID + h * DH + d]);
        }
        __syncthreads();

        float sacc[2][2][4];
#pragma unroll
        for (int mi = 0; mi < 2; mi++)
#pragma unroll
            for (int ni = 0; ni < 2; ni++)
#pragma unroll
                for (int q = 0; q < 4; q++) sacc[mi][ni][q] = 0.f;

#pragma unroll
        for (int ks = 0; ks < 8; ks++) {
            const int kk = ks * 8;
            uint32_t a[2][4], bb[2][2];
#pragma unroll
            for (int mi = 0; mi < 2; mi++) {
                int m = mi * 16;
                a[mi][0] = Qs[(m + ly) * Q_PITCH + kk + lx];
                a[mi][1] = Qs[(m + ly + 8) * Q_PITCH + kk + lx];
                a[mi][2] = Qs[(m + ly) * Q_PITCH + kk + lx + 4];
                a[mi][3] = Qs[(m + ly + 8) * Q_PITCH + kk + lx + 4];
            }
#pragma unroll
            for (int ni = 0; ni < 2; ni++) {
                int n = wid * 16 + ni * 8;
                bb[ni][0] = KVs[(n + ly) * KV_PITCH + kk + lx];
                bb[ni][1] = KVs[(n + ly) * KV_PITCH + kk + lx + 4];
            }
#pragma unroll
            for (int mi = 0; mi < 2; mi++)
#pragma unroll
                for (int ni = 0; ni < 2; ni++)
                    mma_tf32(sacc[mi][ni], a[mi], bb[ni]);
        }

#pragma unroll
        for (int ni = 0; ni < 2; ni++) {
            int col = kt * 128 + wid * 16 + ni * 8 + 2 * lx;
            float mk0 = mask[b * SEQ + col];
            float mk1 = mask[b * SEQ + col + 1];
#pragma unroll
            for (int mi = 0; mi < 2; mi++) {
                int row = mi * 16 + ly;
                Ssc[row * SSC_PITCH + col]           = sacc[mi][ni][0] * 0.125f + mk0;
                Ssc[row * SSC_PITCH + col + 1]       = sacc[mi][ni][1] * 0.125f + mk1;
                Ssc[(row + 8) * SSC_PITCH + col]     = sacc[mi][ni][2] * 0.125f + mk0;
                Ssc[(row + 8) * SSC_PITCH + col + 1] = sacc[mi][ni][3] * 0.125f + mk1;
            }
        }
        __syncthreads();
    }

    // ---- softmax: one warp per row (stride 8), fast exp ----
    for (int r = wid; r < 32; r += 8) {
        float* row = Ssc + r * SSC_PITCH;
        float m = -1e30f;
        for (int c = lane; c < SEQ; c += 32) m = fmaxf(m, row[c]);
#pragma unroll
        for (int o = 16; o >= 1; o >>= 1) m = fmaxf(m, __shfl_xor_sync(0xffffffffu, m, o));
        float s = 0.f;
        for (int c = lane; c < SEQ; c += 32) {
            float e = fast_exp(row[c] - m);
            row[c] = e;
            s += e;
        }
#pragma unroll
        for (int o = 16; o >= 1; o >>= 1) s += __shfl_xor_sync(0xffffffffu, s, o);
        float inv = 1.f / s;
        for (int c = lane; c < SEQ; c += 32) row[c] *= inv;
    }
    __syncthreads();

    // ---- write probs ----
    for (int i = tid; i < 32 * 1024; i += 256)
        probs[i] = Ssc[(i >> 10) * SSC_PITCH + (i & 1023)];

    // ---- Phase 2: ctx = P @ V ----
    float cacc[2][4];
#pragma unroll
    for (int mi = 0; mi < 2; mi++)
#pragma unroll
        for (int q = 0; q < 4; q++) cacc[mi][q] = 0.f;

    for (int vt = 0; vt < 8; vt++) {
        __syncthreads();
        for (int i = tid; i < 128 * 64; i += 256) {
            int r = i >> 6, d = i & 63;
            KVs[r * KV_PITCH + d] =
                f2tf(V[(size_t)(b * SEQ + vt * 128 + r) * HID + h * DH + d]);
        }
        __syncthreads();

#pragma unroll
        for (int ks = 0; ks < 16; ks++) {
            const int kk = vt * 128 + ks * 8;
            uint32_t a[2][4], bb[2];
#pragma unroll
            for (int mi = 0; mi < 2; mi++) {
                int m = mi * 16;
                a[mi][0] = f2tf(Ssc[(m + ly) * SSC_PITCH + kk + lx]);
                a[mi][1] = f2tf(Ssc[(m + ly + 8) * SSC_PITCH + kk + lx]);
                a[mi][2] = f2tf(Ssc[(m + ly) * SSC_PITCH + kk + lx + 4]);
                a[mi][3] = f2tf(Ssc[(m + ly + 8) * SSC_PITCH + kk + lx + 4]);
            }
            bb[0] = KVs[(ks * 8 + lx) * KV_PITCH + wid * 8 + ly];
            bb[1] = KVs[(ks * 8 + lx + 4) * KV_PITCH + wid * 8 + ly];
#pragma unroll
            for (int mi = 0; mi < 2; mi++)
                mma_tf32(cacc[mi], a[mi], bb);
        }
    }

#pragma unroll
    for (int mi = 0; mi < 2; mi++) {
        int row = qb * 32 + mi * 16 + ly;
        int d = h * DH + wid * 8 + 2 * lx;
        float2 v0 = {cacc[mi][0], cacc[mi][1]};
        float2 v1 = {cacc[mi][2], cacc[mi][3]};
        *(float2*)(ctx + (size_t)(b * SEQ + row) * HID + d) = v0;
        *(float2*)(ctx + (size_t)(b * SEQ + row + 8) * HID + d) = v1;
    }
}

// ---------------------------------------------------------------------------
extern "C" void kernel_launch(void* const* d_in, const int* in_sizes, int n_in,
                              void* d_out, int out_size) {
    (void)in_sizes; (void)n_in; (void)out_size;

    const float* m1 = (const float*)d_in[1];
    const float* m2 = (const float*)d_in[3];

    QKVArgs a;
    a.x[0] = (const float*)d_in[0];
    a.x[1] = (const float*)d_in[2];
    for (int i = 0; i < 6; i++) {
        a.w[i] = (const float*)d_in[4 + 2 * i];
        a.b[i] = (const float*)d_in[5 + 2 * i];
    }

    cudaFuncSetAttribute(attn_kernel, cudaFuncAttributeMaxDynamicSharedMemorySize,
                         ATTN_SMEM);

    qkv_gemm<<<dim3(8, 32, 6), 256>>>(a);
    attn_kernel<<<dim3(32, 16, 8), 256, ATTN_SMEM>>>(m1, m2, (float*)d_out);
}

// round 3
// speedup vs baseline: 3.1952x; 2.3250x over previous
#include <cuda_runtime.h>
#include <cstdint>

#define HID 1024
#define SEQ 1024
#define NB  4
#define NH  16
#define DH  64

// Scratch for q1,k1,v1,q2,k2,v2 : 6 x [B*S, HID] fp32 = ~100 MB
__device__ float g_qkv[6][NB * SEQ * HID];

struct QKVArgs {
    const float* x[2];
    const float* w[6];
    const float* b[6];
};

__device__ __forceinline__ uint32_t f2tf(float x) {
    uint32_t t;
    asm("cvt.rna.tf32.f32 %0, %1;" : "=r"(t) : "f"(x));
    return t;
}

__device__ __forceinline__ void mma_tf32(float* c, const uint32_t* a, const uint32_t* b) {
    asm volatile(
        "mma.sync.aligned.m16n8k8.row.col.f32.tf32.tf32.f32 "
        "{%0,%1,%2,%3}, {%4,%5,%6,%7}, {%8,%9}, {%0,%1,%2,%3};\n"
        : "+f"(c[0]), "+f"(c[1]), "+f"(c[2]), "+f"(c[3])
        : "r"(a[0]), "r"(a[1]), "r"(a[2]), "r"(a[3]), "r"(b[0]), "r"(b[1]));
}

// exp(x) via 2^t with degree-5 poly; ~2e-6 abs err, no MUFU.
__device__ __forceinline__ float fast_exp(float x) {
    x = fmaxf(x, -80.f);
    float t = x * 1.44269504f;
    float r = rintf(t);
    float y = (t - r) * 0.69314718f;
    float p = 8.3333333e-3f;
    p = fmaf(p, y, 4.1666667e-2f);
    p = fmaf(p, y, 1.6666667e-1f);
    p = fmaf(p, y, 5.0e-1f);
    p = fmaf(p, y, 1.0f);
    p = fmaf(p, y, 1.0f);
    return __int_as_float(__float_as_int(p) + (((int)r) << 23));
}

// ---------------------------------------------------------------------------
// QKV projection: C = X @ W + b (M=4096, N=1024, K=1024), TF32 mma.
// CTA tile 128x64, BK=32, 256 threads (8 warps 4x2), warp tile 32x32.
// Double-buffered smem, software-pipelined gmem loads.
// ---------------------------------------------------------------------------
#define GA_PITCH 36
#define GB_PITCH 72
#define GA_WORDS (128 * GA_PITCH)
#define GB_WORDS (32 * GB_PITCH)
#define GEMM_SMEM ((2 * GA_WORDS + 2 * GB_WORDS) * 4)

__global__ __launch_bounds__(256, 2) void qkv_gemm(QKVArgs args) {
    extern __shared__ uint32_t gsm[];
    uint32_t* As = gsm;                 // 2 x [128][36]
    uint32_t* Bs = gsm + 2 * GA_WORDS;  // 2 x [32][72]

    const int p = blockIdx.z;
    const float* X    = args.x[p / 3];
    const float* W    = args.w[p];
    const float* bias = args.b[p];
    float* C = g_qkv[p];

    const int tid = threadIdx.x;
    const int wid = tid >> 5;
    const int lane = tid & 31;
    const int ly = lane >> 2;
    const int lx = lane & 3;
    const int wm = (wid & 3) * 32;
    const int wn = (wid >> 2) * 32;
    const int bm = blockIdx.y << 7;
    const int bn = blockIdx.x << 6;

    const int arow = tid >> 3, ac4 = (tid & 7) << 2;      // A: 128x32
    const int brow = tid >> 4, bc4 = (tid & 15) << 2;     // B: 32x64

    float4 ra[4], rb[2];

    // prologue: load + store k0=0 into buf0
#pragma unroll
    for (int i = 0; i < 4; i++)
        ra[i] = *(const float4*)(X + (size_t)(bm + arow + i * 32) * HID + ac4);
#pragma unroll
    for (int i = 0; i < 2; i++)
        rb[i] = *(const float4*)(W + (size_t)(brow + i * 16) * HID + bn + bc4);
#pragma unroll
    for (int i = 0; i < 4; i++) {
        uint4 t = {f2tf(ra[i].x), f2tf(ra[i].y), f2tf(ra[i].z), f2tf(ra[i].w)};
        *(uint4*)&As[(arow + i * 32) * GA_PITCH + ac4] = t;
    }
#pragma unroll
    for (int i = 0; i < 2; i++) {
        uint4 t = {f2tf(rb[i].x), f2tf(rb[i].y), f2tf(rb[i].z), f2tf(rb[i].w)};
        *(uint4*)&Bs[(brow + i * 16) * GB_PITCH + bc4] = t;
    }
    __syncthreads();

    float acc[2][4][4];
#pragma unroll
    for (int i = 0; i < 2; i++)
#pragma unroll
        for (int j = 0; j < 4; j++)
#pragma unroll
            for (int q = 0; q < 4; q++) acc[i][j][q] = 0.f;

    for (int k0 = 0; k0 < HID; k0 += 32) {
        const int cur = (k0 >> 5) & 1;
        const uint32_t* Ab = As + cur * GA_WORDS;
        const uint32_t* Bb = Bs + cur * GB_WORDS;
        const bool more = (k0 + 32) < HID;

        if (more) {
#pragma unroll
            for (int i = 0; i < 4; i++)
                ra[i] = *(const float4*)(X + (size_t)(bm + arow + i * 32) * HID + k0 + 32 + ac4);
#pragma unroll
            for (int i = 0; i < 2; i++)
                rb[i] = *(const float4*)(W + (size_t)(k0 + 32 + brow + i * 16) * HID + bn + bc4);
        }

#pragma unroll
        for (int ks = 0; ks < 4; ks++) {
            const int kk = ks * 8;
            uint32_t a[2][4], b[4][2];
#pragma unroll
            for (int mi = 0; mi < 2; mi++) {
                int m = wm + mi * 16;
                a[mi][0] = Ab[(m + ly) * GA_PITCH + kk + lx];
                a[mi][1] = Ab[(m + ly + 8) * GA_PITCH + kk + lx];
                a[mi][2] = Ab[(m + ly) * GA_PITCH + kk + lx + 4];
                a[mi][3] = Ab[(m + ly + 8) * GA_PITCH + kk + lx + 4];
            }
#pragma unroll
            for (int ni = 0; ni < 4; ni++) {
                int n = wn + ni * 8;
                b[ni][0] = Bb[(kk + lx) * GB_PITCH + n + ly];
                b[ni][1] = Bb[(kk + lx + 4) * GB_PITCH + n + ly];
            }
#pragma unroll
            for (int mi = 0; mi < 2; mi++)
#pragma unroll
                for (int ni = 0; ni < 4; ni++)
                    mma_tf32(acc[mi][ni], a[mi], b[ni]);
        }

        if (more) {
            uint32_t* An = As + (cur ^ 1) * GA_WORDS;
            uint32_t* Bn = Bs + (cur ^ 1) * GB_WORDS;
#pragma unroll
            for (int i = 0; i < 4; i++) {
                uint4 t = {f2tf(ra[i].x), f2tf(ra[i].y), f2tf(ra[i].z), f2tf(ra[i].w)};
                *(uint4*)&An[(arow + i * 32) * GA_PITCH + ac4] = t;
            }
#pragma unroll
            for (int i = 0; i < 2; i++) {
                uint4 t = {f2tf(rb[i].x), f2tf(rb[i].y), f2tf(rb[i].z), f2tf(rb[i].w)};
                *(uint4*)&Bn[(brow + i * 16) * GB_PITCH + bc4] = t;
            }
        }
        __syncthreads();
    }

#pragma unroll
    for (int mi = 0; mi < 2; mi++) {
#pragma unroll
        for (int ni = 0; ni < 4; ni++) {
            int m = bm + wm + mi * 16 + ly;
            int n = bn + wn + ni * 8 + 2 * lx;
            float b0 = bias[n], b1 = bias[n + 1];
            float2 v0 = {acc[mi][ni][0] + b0, acc[mi][ni][1] + b1};
            float2 v1 = {acc[mi][ni][2] + b0, acc[mi][ni][3] + b1};
            *(float2*)(C + (size_t)m * HID + n) = v0;
            *(float2*)(C + (size_t)(m + 8) * HID + n) = v1;
        }
    }
}

// ---------------------------------------------------------------------------
// Fused cross-attention, double-buffered K/V staging, TF32 mma.
// One CTA = (stream, b, h, 32 q-rows). 256 threads.
// Phase1: warp tile 32x16 over 128-col K tiles. Softmax exact (fast exp).
// Phase2: k-split across warps (warp owns 16 k-rows of each V tile),
//         smem partial reduction at the end.
// ---------------------------------------------------------------------------
#define SSC_PITCH 1028
#define Q_PITCH   68
#define KV_PITCH  76
#define KV_WORDS  (128 * KV_PITCH)
#define RED_PITCH 65
#define ATTN_SMEM ((32 * SSC_PITCH + 32 * Q_PITCH + 2 * KV_WORDS) * 4)

__global__ __launch_bounds__(256) void attn_kernel(const float* __restrict__ mask1,
                                                   const float* __restrict__ mask2,
                                                   float* __restrict__ out) {
    extern __shared__ float sm[];
    float*    Ssc = sm;                                   // [32][1028]
    uint32_t* Qs  = (uint32_t*)(sm + 32 * SSC_PITCH);     // [32][68] tf32
    uint32_t* KVs = Qs + 32 * Q_PITCH;                    // 2 x [128][76]
    float*    red = (float*)KVs;                          // 8 x [32][65] (reused)

    const int qb = blockIdx.x;
    const int h  = blockIdx.y;
    const int b  = blockIdx.z >> 1;
    const int st = blockIdx.z & 1;

    const float* Q    = g_qkv[st * 3];
    const float* K    = st ? g_qkv[1] : g_qkv[4];
    const float* V    = st ? g_qkv[2] : g_qkv[5];
    const float* mask = st ? mask1 : mask2;

    float* probs = out + 8388608 + (size_t)st * 67108864
                 + ((size_t)(b * NH + h) * SEQ + qb * 32) * SEQ;
    float* ctx = out + (size_t)st * 4194304;

    const int tid = threadIdx.x;
    const int wid = tid >> 5;
    const int lane = tid & 31;
    const int ly = lane >> 2;
    const int lx = lane & 3;

    const int srow = tid >> 4, sc4 = (tid & 15) << 2;  // staging: 2048 f4 / 256 thr = 8 each

    // Stage Q (tf32): Qs[r][d]
    for (int i = tid; i < 32 * 16; i += 256) {
        int r = i >> 4, c4 = (i & 15) << 2;
        float4 v = *(const float4*)(Q + (size_t)(b * SEQ + qb * 32 + r) * HID + h * DH + c4);
        uint4 t = {f2tf(v.x), f2tf(v.y), f2tf(v.z), f2tf(v.w)};
        *(uint4*)&Qs[r * Q_PITCH + c4] = t;
    }

    float4 stg[8];

    // ---- Phase 1: scores = QK^T/8 + mask ----
    // prologue: K tile 0
#pragma unroll
    for (int i = 0; i < 8; i++)
        stg[i] = *(const float4*)(K + (size_t)(b * SEQ + srow + i * 16) * HID + h * DH + sc4);
#pragma unroll
    for (int i = 0; i < 8; i++) {
        uint4 t = {f2tf(stg[i].x), f2tf(stg[i].y), f2tf(stg[i].z), f2tf(stg[i].w)};
        *(uint4*)&KVs[(srow + i * 16) * KV_PITCH + sc4] = t;
    }
    __syncthreads();

    for (int kt = 0; kt < 8; kt++) {
        const int cur = kt & 1;
        const uint32_t* KB = KVs + cur * KV_WORDS;
        const bool more = kt < 7;

        if (more) {
#pragma unroll
            for (int i = 0; i < 8; i++)
                stg[i] = *(const float4*)(K + (size_t)(b * SEQ + (kt + 1) * 128 + srow + i * 16) * HID + h * DH + sc4);
        }

        float sacc[2][2][4];
#pragma unroll
        for (int mi = 0; mi < 2; mi++)
#pragma unroll
            for (int ni = 0; ni < 2; ni++)
#pragma unroll
                for (int q = 0; q < 4; q++) sacc[mi][ni][q] = 0.f;

#pragma unroll
        for (int ks = 0; ks < 8; ks++) {
            const int kk = ks * 8;
            uint32_t a[2][4], bb[2][2];
#pragma unroll
            for (int mi = 0; mi < 2; mi++) {
                int m = mi * 16;
                a[mi][0] = Qs[(m + ly) * Q_PITCH + kk + lx];
                a[mi][1] = Qs[(m + ly + 8) * Q_PITCH + kk + lx];
                a[mi][2] = Qs[(m + ly) * Q_PITCH + kk + lx + 4];
                a[mi][3] = Qs[(m + ly + 8) * Q_PITCH + kk + lx + 4];
            }
#pragma unroll
            for (int ni = 0; ni < 2; ni++) {
                int n = wid * 16 + ni * 8;
                bb[ni][0] = KB[(n + ly) * KV_PITCH + kk + lx];
                bb[ni][1] = KB[(n + ly) * KV_PITCH + kk + lx + 4];
            }
#pragma unroll
            for (int mi = 0; mi < 2; mi++)
#pragma unroll
                for (int ni = 0; ni < 2; ni++)
                    mma_tf32(sacc[mi][ni], a[mi], bb[ni]);
        }

#pragma unroll
        for (int ni = 0; ni < 2; ni++) {
            int col = kt * 128 + wid * 16 + ni * 8 + 2 * lx;
            float mk0 = mask[b * SEQ + col];
            float mk1 = mask[b * SEQ + col + 1];
#pragma unroll
            for (int mi = 0; mi < 2; mi++) {
                int row = mi * 16 + ly;
                Ssc[row * SSC_PITCH + col]           = sacc[mi][ni][0] * 0.125f + mk0;
                Ssc[row * SSC_PITCH + col + 1]       = sacc[mi][ni][1] * 0.125f + mk1;
                Ssc[(row + 8) * SSC_PITCH + col]     = sacc[mi][ni][2] * 0.125f + mk0;
                Ssc[(row + 8) * SSC_PITCH + col + 1] = sacc[mi][ni][3] * 0.125f + mk1;
            }
        }

        if (more) {
            uint32_t* KN = KVs + (cur ^ 1) * KV_WORDS;
#pragma unroll
            for (int i = 0; i < 8; i++) {
                uint4 t = {f2tf(stg[i].x), f2tf(stg[i].y), f2tf(stg[i].z), f2tf(stg[i].w)};
                *(uint4*)&KN[(srow + i * 16) * KV_PITCH + sc4] = t;
            }
        }
        __syncthreads();
    }

    // ---- softmax: one warp per row (stride 8), fast exp ----
    for (int r = wid; r < 32; r += 8) {
        float* row = Ssc + r * SSC_PITCH;
        float m = -1e30f;
        for (int c = lane; c < SEQ; c += 32) m = fmaxf(m, row[c]);
#pragma unroll
        for (int o = 16; o >= 1; o >>= 1) m = fmaxf(m, __shfl_xor_sync(0xffffffffu, m, o));
        float s = 0.f;
        for (int c = lane; c < SEQ; c += 32) {
            float e = fast_exp(row[c] - m);
            row[c] = e;
            s += e;
        }
#pragma unroll
        for (int o = 16; o >= 1; o >>= 1) s += __shfl_xor_sync(0xffffffffu, s, o);
        float inv = 1.f / s;
        for (int c = lane; c < SEQ; c += 32) row[c] *= inv;
    }
    __syncthreads();

    // ---- write probs + convert P to tf32 in place ----
    for (int i = tid; i < 8192; i += 256) {
        int row = i >> 8, c4 = (i & 255) << 2;
        float4 v = *(float4*)&Ssc[row * SSC_PITCH + c4];
        *(float4*)&probs[row * 1024 + c4] = v;
        uint4 t = {f2tf(v.x), f2tf(v.y), f2tf(v.z), f2tf(v.w)};
        *(uint4*)&Ssc[row * SSC_PITCH + c4] = t;
    }

    // ---- Phase 2: ctx = P @ V, k-split across warps ----
    // prologue: V tile 0 (KV buffers free: phase1 done; sync below orders convert too)
#pragma unroll
    for (int i = 0; i < 8; i++)
        stg[i] = *(const float4*)(V + (size_t)(b * SEQ + srow + i * 16) * HID + h * DH + sc4);
#pragma unroll
    for (int i = 0; i < 8; i++) {
        uint4 t = {f2tf(stg[i].x), f2tf(stg[i].y), f2tf(stg[i].z), f2tf(stg[i].w)};
        *(uint4*)&KVs[(srow + i * 16) * KV_PITCH + sc4] = t;
    }
    __syncthreads();

    float cacc[2][8][4];
#pragma unroll
    for (int mi = 0; mi < 2; mi++)
#pragma unroll
        for (int ni = 0; ni < 8; ni++)
#pragma unroll
            for (int q = 0; q < 4; q++) cacc[mi][ni][q] = 0.f;

    const uint32_t* Su = (const uint32_t*)Ssc;

    for (int vt = 0; vt < 8; vt++) {
        const int cur = vt & 1;
        const uint32_t* VB = KVs + cur * KV_WORDS;
        const bool more = vt < 7;

        if (more) {
#pragma unroll
            for (int i = 0; i < 8; i++)
                stg[i] = *(const float4*)(V + (size_t)(b * SEQ + (vt + 1) * 128 + srow + i * 16) * HID + h * DH + sc4);
        }

#pragma unroll
        for (int ks2 = 0; ks2 < 2; ks2++) {
            const int kloc = wid * 16 + ks2 * 8;
            const int kg = vt * 128 + kloc;
            uint32_t a[2][4], bb[8][2];
#pragma unroll
            for (int mi = 0; mi < 2; mi++) {
                int m = mi * 16;
                a[mi][0] = Su[(m + ly) * SSC_PITCH + kg + lx];
                a[mi][1] = Su[(m + ly + 8) * SSC_PITCH + kg + lx];
                a[mi][2] = Su[(m + ly) * SSC_PITCH + kg + lx + 4];
                a[mi][3] = Su[(m + ly + 8) * SSC_PITCH + kg + lx + 4];
            }
#pragma unroll
            for (int ni = 0; ni < 8; ni++) {
                bb[ni][0] = VB[(kloc + lx) * KV_PITCH + ni * 8 + ly];
                bb[ni][1] = VB[(kloc + lx + 4) * KV_PITCH + ni * 8 + ly];
            }
#pragma unroll
            for (int mi = 0; mi < 2; mi++)
#pragma unroll
                for (int ni = 0; ni < 8; ni++)
                    mma_tf32(cacc[mi][ni], a[mi], bb[ni]);
        }

        if (more) {
            uint32_t* VN = KVs + (cur ^ 1) * KV_WORDS;
#pragma unroll
            for (int i = 0; i < 8; i++) {
                uint4 t = {f2tf(stg[i].x), f2tf(stg[i].y), f2tf(stg[i].z), f2tf(stg[i].w)};
                *(uint4*)&VN[(srow + i * 16) * KV_PITCH + sc4] = t;
            }
        }
        __syncthreads();
    }

    // ---- reduce partial ctx across warps via smem (KV region reused) ----
#pragma unroll
    for (int mi = 0; mi < 2; mi++)
#pragma unroll
        for (int ni = 0; ni < 8; ni++)
#pragma unroll
            for (int q = 0; q < 4; q++) {
                int row = mi * 16 + ly + (q >> 1) * 8;
                int col = ni * 8 + 2 * lx + (q & 1);
                red[wid * (32 * RED_PITCH) + row * RED_PITCH + col] = cacc[mi][ni][q];
            }
    __syncthreads();

    {
        int row = tid >> 3;
        int col = (tid & 7) << 3;
        float s[8] = {0.f, 0.f, 0.f, 0.f, 0.f, 0.f, 0.f, 0.f};
#pragma unroll
        for (int w = 0; w < 8; w++) {
            const float* rp = red + w * (32 * RED_PITCH) + row * RED_PITCH + col;
#pragma unroll
            for (int j = 0; j < 8; j++) s[j] += rp[j];
        }
        float4 v0 = {s[0], s[1], s[2], s[3]};
        float4 v1 = {s[4], s[5], s[6], s[7]};
        float* dst = ctx + (size_t)(b * SEQ + qb * 32 + row) * HID + h * DH + col;
        *(float4*)dst = v0;
        *(float4*)(dst + 4) = v1;
    }
}

// ---------------------------------------------------------------------------
extern "C" void kernel_launch(void* const* d_in, const int* in_sizes, int n_in,
                              void* d_out, int out_size) {
    (void)in_sizes; (void)n_in; (void)out_size;

    const float* m1 = (const float*)d_in[1];
    const float* m2 = (const float*)d_in[3];

    QKVArgs a;
    a.x[0] = (const float*)d_in[0];
    a.x[1] = (const float*)d_in[2];
    for (int i = 0; i < 6; i++) {
        a.w[i] = (const float*)d_in[4 + 2 * i];
        a.b[i] = (const float*)d_in[5 + 2 * i];
    }

    cudaFuncSetAttribute(qkv_gemm, cudaFuncAttributeMaxDynamicSharedMemorySize,
                         GEMM_SMEM);
    cudaFuncSetAttribute(attn_kernel, cudaFuncAttributeMaxDynamicSharedMemorySize,
                         ATTN_SMEM);

    qkv_gemm<<<dim3(16, 32, 6), 256, GEMM_SMEM>>>(a);
    attn_kernel<<<dim3(32, 16, 8), 256, ATTN_SMEM>>>(m1, m2, (float*)d_out);
}